// round 15
// baseline (speedup 1.0000x reference)
#include <cuda_runtime.h>
#include <cstdint>

// ---------------------------------------------------------------------------
// 4-layer LSTM (B=128, T=1024, D=128, H=[100,100,200,200]) + dense head.
// R14: bf16 GEMM staging hoisted out of the hot loop — per-layer pre-split
// kernels write A and W as k-paired bf16x2 hi/lo planes in gmem (k2
// permutation + column map baked in, W zero-padded to the tile grid), so the
// GEMM does LDG->STS->LDS->MMA only. Scans identical to R7/R13 baseline.
// ---------------------------------------------------------------------------

#define TLEN 1024
#define BSZ  128
#define HPAD 256
#define MTOT (BSZ * TLEN)

typedef unsigned long long u64;
typedef unsigned int u32;

__device__ float g_zx[(size_t)BSZ * TLEN * 800];  // x@Wx+b, layout [b][t][j][4]
__device__ float g_seq[(size_t)BSZ * TLEN * 200]; // layer output sequence
__device__ float g_hbuf[BSZ * HPAD];              // final h for dense head

// pre-split planes (max K2P = 104 for K=200; max NWP = 896 for N=800)
__device__ u32 g_Ah[(size_t)MTOT * 104];
__device__ u32 g_Al[(size_t)MTOT * 104];
__device__ u32 g_Wh[104 * 896];
__device__ u32 g_Wl[104 * 896];

#define FMA2(d, a, b, c) \
    asm("fma.rn.f32x2 %0, %1, %2, %3;" : "=l"(d) : "l"(a), "l"(b), "l"(c))

__device__ __forceinline__ u64 pack2(float lo, float hi) {
    u64 d;
    asm("mov.b64 %0, {%1, %2};" : "=l"(d)
        : "r"(__float_as_uint(lo)), "r"(__float_as_uint(hi)));
    return d;
}
__device__ __forceinline__ float2 unpack2(u64 v) {
    unsigned lo, hi;
    asm("mov.b64 {%0, %1}, %2;" : "=r"(lo), "=r"(hi) : "l"(v));
    return make_float2(__uint_as_float(lo), __uint_as_float(hi));
}

__device__ __forceinline__ float sigm(float x) {
    return __fdividef(1.0f, 1.0f + __expf(-x));
}
__device__ __forceinline__ float tanh_fast(float x) {
    return 1.0f - __fdividef(2.0f, __expf(2.0f * x) + 1.0f);
}

__device__ __forceinline__ void mbar_wait_parity_cluster(uint32_t bar, uint32_t parity) {
    uint32_t done;
    asm volatile(
        "{\n\t.reg .pred p;\n\t"
        "mbarrier.try_wait.parity.acquire.cluster.shared::cta.b64 p, [%1], %2;\n\t"
        "selp.b32 %0, 1, 0, p;\n\t}"
        : "=r"(done) : "r"(bar), "r"(parity) : "memory");
    if (!done) {
        asm volatile(
            "{\n\t.reg .pred P1;\n\t"
            "WAIT_LOOP_%=:\n\t"
            "mbarrier.try_wait.parity.acquire.cluster.shared::cta.b64 P1, [%0], %1, 0x989680;\n\t"
            "@P1 bra.uni WAIT_DONE_%=;\n\t"
            "bra.uni WAIT_LOOP_%=;\n\t"
            "WAIT_DONE_%=:\n\t}"
            :: "r"(bar), "r"(parity) : "memory");
    }
}

// ---------------------------------------------------------------------------
// bf16 helpers
// ---------------------------------------------------------------------------
__device__ __forceinline__ u32 bf16x2_of(float f0, float f1) {
    u32 r;   // f0 -> low half, f1 -> high half
    asm("cvt.rn.bf16x2.f32 %0, %1, %2;" : "=r"(r) : "f"(f1), "f"(f0));
    return r;
}
__device__ __forceinline__ float bf_lo_f(u32 v) { return __uint_as_float(v << 16); }
__device__ __forceinline__ float bf_hi_f(u32 v) { return __uint_as_float(v & 0xffff0000u); }

__device__ __forceinline__ void mma_bf16(float* c, const u32* a, const u32* b) {
    asm volatile(
        "mma.sync.aligned.m16n8k16.row.col.f32.bf16.bf16.f32 "
        "{%0,%1,%2,%3}, {%4,%5,%6,%7}, {%8,%9}, {%0,%1,%2,%3};"
        : "+f"(c[0]), "+f"(c[1]), "+f"(c[2]), "+f"(c[3])
        : "r"(a[0]), "r"(a[1]), "r"(a[2]), "r"(a[3]), "r"(b[0]), "r"(b[1]));
}

// slot -> k2 offset within an 8-slot chunk (inverse of p(k2)=(k2&3)*2+(k2>>2))
__device__ __forceinline__ int invp(int p) {
    return (p & 1) ? (4 + (p >> 1)) : (p >> 1);
}

// ---------------------------------------------------------------------------
// Pre-split A: float [M][K] -> u32 hi/lo planes [M][K2P] (bf16x2 k-pairs,
// permuted within each 8-slot chunk; zero-padded beyond K).
// ---------------------------------------------------------------------------
__global__ void split_a(const float* __restrict__ Ain, int K, int K2P, int use_seq)
{
    const float* __restrict__ A = use_seq ? g_seq : Ain;
    size_t idx = (size_t)blockIdx.x * blockDim.x + threadIdx.x;
    size_t total = (size_t)MTOT * K2P;
    if (idx >= total) return;
    int s   = (int)(idx % K2P);
    size_t row = idx / K2P;
    int k2  = (s & ~7) + invp(s & 7);
    int k   = 2 * k2;
    float x0 = (k     < K) ? A[row * K + k]     : 0.0f;
    float x1 = (k + 1 < K) ? A[row * K + k + 1] : 0.0f;
    u32 hi = bf16x2_of(x0, x1);
    u32 lo = bf16x2_of(x0 - bf_lo_f(hi), x1 - bf_hi_f(hi));
    g_Ah[idx] = hi;
    g_Al[idx] = lo;
}

// ---------------------------------------------------------------------------
// Pre-split W: float [K][Nw] -> u32 hi/lo planes [K2P][NWP] with the output
// column map baked in (col n <- W col (n&3)*Hn + (n>>2)); zero-padded.
// ---------------------------------------------------------------------------
__global__ void split_w(const float* __restrict__ W,
                        int K, int N, int Hn, int NWP, int K2P)
{
    int idx = blockIdx.x * blockDim.x + threadIdx.x;
    int total = K2P * NWP;
    if (idx >= total) return;
    int s = idx / NWP;
    int n = idx % NWP;
    int k2 = (s & ~7) + invp(s & 7);
    int k  = 2 * k2;
    int wsrc = (n & 3) * Hn + (n >> 2);
    float x0 = (k     < K && n < N) ? W[(size_t)k * N + wsrc]       : 0.0f;
    float x1 = (k + 1 < K && n < N) ? W[(size_t)(k + 1) * N + wsrc] : 0.0f;
    u32 hi = bf16x2_of(x0, x1);
    u32 lo = bf16x2_of(x0 - bf_lo_f(hi), x1 - bf_hi_f(hi));
    g_Wh[idx] = hi;
    g_Wl[idx] = lo;
}

// ---------------------------------------------------------------------------
// Lean bf16 tensor-core GEMM (3-term split hh+lh+hl) on pre-split planes.
// C[M, n] = A@W + bias (permuted) -> g_zx. 128x128 CTA tile, 256 threads,
// 8 warps (32x64), KC=16 double-buffered. No conversion in the hot loop.
// ---------------------------------------------------------------------------
template <int K>
__global__ void __launch_bounds__(256, 2)
gemm_bf16p(const float* __restrict__ bias, int N, int NWP, int Hn)
{
    constexpr int KC  = 16;
    constexpr int NCH = (K + KC - 1) / KC;
    constexpr int K2P = NCH * 8;
    constexpr int LDQ = 10;                   // u32 row stride (8 + pad, 8B-aligned)

    __shared__ __align__(16) u32 Ah[2][128][LDQ], Al[2][128][LDQ];
    __shared__ __align__(16) u32 Bh[2][128][LDQ], Bl[2][128][LDQ];

    const int tid  = threadIdx.x;
    const int m0   = blockIdx.y * 128, n0 = blockIdx.x * 128;
    const int warp = tid >> 5, lane = tid & 31;
    const int g    = lane >> 2, tig = lane & 3;
    const int wm   = (warp >> 1) * 32, wn = (warp & 1) * 64;

    // staging roles: d = row/col (tid>>1), half = k-half (tid&1: 4 slots each)
    const int sd = tid >> 1, sh = tid & 1;

    u32 aRh[4], aRl[4], bRh[4], bRl[4];

    auto ldA = [&](int c) {
        size_t off = (size_t)(m0 + sd) * K2P + c * 8 + sh * 4;
        uint2 h0 = *reinterpret_cast<const uint2*>(&g_Ah[off]);
        uint2 h1 = *reinterpret_cast<const uint2*>(&g_Ah[off + 2]);
        uint2 l0 = *reinterpret_cast<const uint2*>(&g_Al[off]);
        uint2 l1 = *reinterpret_cast<const uint2*>(&g_Al[off + 2]);
        aRh[0] = h0.x; aRh[1] = h0.y; aRh[2] = h1.x; aRh[3] = h1.y;
        aRl[0] = l0.x; aRl[1] = l0.y; aRl[2] = l1.x; aRl[3] = l1.y;
    };
    auto ldB = [&](int c) {
        #pragma unroll
        for (int e = 0; e < 4; ++e) {
            int s = c * 8 + sh * 4 + e;
            bRh[e] = g_Wh[(size_t)s * NWP + n0 + sd];
            bRl[e] = g_Wl[(size_t)s * NWP + n0 + sd];
        }
    };
    auto stA = [&](int buf) {
        #pragma unroll
        for (int e = 0; e < 4; ++e) {
            Ah[buf][sd][sh * 4 + e] = aRh[e];
            Al[buf][sd][sh * 4 + e] = aRl[e];
        }
    };
    auto stB = [&](int buf) {
        #pragma unroll
        for (int e = 0; e < 4; ++e) {
            Bh[buf][sd][sh * 4 + e] = bRh[e];
            Bl[buf][sd][sh * 4 + e] = bRl[e];
        }
    };

    ldA(0); ldB(0);
    stA(0); stB(0);
    __syncthreads();

    float acc[2][8][4];
    #pragma unroll
    for (int mt = 0; mt < 2; ++mt)
        #pragma unroll
        for (int nt = 0; nt < 8; ++nt)
            #pragma unroll
            for (int i = 0; i < 4; ++i) acc[mt][nt][i] = 0.0f;

    for (int c = 0; c < NCH; ++c) {
        const int buf = c & 1;
        if (c + 1 < NCH) { ldA(c + 1); ldB(c + 1); }

        u32 ah[2][4], al[2][4];
        #pragma unroll
        for (int mt = 0; mt < 2; ++mt) {
            int row = wm + mt * 16 + g;
            uint2 t;
            t = *reinterpret_cast<const uint2*>(&Ah[buf][row][2 * tig]);
            ah[mt][0] = t.x; ah[mt][2] = t.y;
            t = *reinterpret_cast<const uint2*>(&Ah[buf][row + 8][2 * tig]);
            ah[mt][1] = t.x; ah[mt][3] = t.y;
            t = *reinterpret_cast<const uint2*>(&Al[buf][row][2 * tig]);
            al[mt][0] = t.x; al[mt][2] = t.y;
            t = *reinterpret_cast<const uint2*>(&Al[buf][row + 8][2 * tig]);
            al[mt][1] = t.x; al[mt][3] = t.y;
        }
        #pragma unroll
        for (int nt = 0; nt < 8; ++nt) {
            int coln = wn + nt * 8 + g;
            u32 bh[2], bl[2];
            uint2 t;
            t = *reinterpret_cast<const uint2*>(&Bh[buf][coln][2 * tig]);
            bh[0] = t.x; bh[1] = t.y;
            t = *reinterpret_cast<const uint2*>(&Bl[buf][coln][2 * tig]);
            bl[0] = t.x; bl[1] = t.y;
            #pragma unroll
            for (int mt = 0; mt < 2; ++mt) {
                mma_bf16(acc[mt][nt], ah[mt], bh);
                mma_bf16(acc[mt][nt], al[mt], bh);
                mma_bf16(acc[mt][nt], ah[mt], bl);
            }
        }
        if (c + 1 < NCH) { stA(buf ^ 1); stB(buf ^ 1); }
        __syncthreads();
    }

    // epilogue: bias (permuted) + store
    #pragma unroll
    for (int nt = 0; nt < 8; ++nt) {
        int col = n0 + wn + nt * 8 + tig * 2;
        if (col >= N) continue;
        float b0 = bias[(col & 3) * Hn + (col >> 2)];
        float b1 = bias[((col + 1) & 3) * Hn + ((col + 1) >> 2)];
        #pragma unroll
        for (int mt = 0; mt < 2; ++mt) {
            int row = m0 + wm + mt * 16 + g;
            float2 v0 = make_float2(acc[mt][nt][0] + b0, acc[mt][nt][1] + b1);
            float2 v1 = make_float2(acc[mt][nt][2] + b0, acc[mt][nt][3] + b1);
            *reinterpret_cast<float2*>(&g_zx[(size_t)row * N + col])       = v0;
            *reinterpret_cast<float2*>(&g_zx[(size_t)(row + 8) * N + col]) = v1;
        }
    }
}

// ---------------------------------------------------------------------------
// H=100 scan (R7, proven): 1 CTA per batch row, Wh in regs (k-paired f32x2),
// h in SMEM, zx float4 with 2-deep register prefetch ring.
// ---------------------------------------------------------------------------
__global__ void __launch_bounds__(512, 1)
scan100(const float* __restrict__ Wh)
{
    __shared__ __align__(16) float  h_s[104];
    __shared__ __align__(16) float4 zp[5][100];

    const int tid = threadIdx.x;
    const int b   = blockIdx.x;
    const int s   = tid / 100;
    const int j   = tid % 100;
    const bool ga  = (tid < 500);
    const bool red = (tid < 100);

    u64 w2[10][4];
    if (ga) {
        const int k0 = s * 20;
        #pragma unroll
        for (int kp = 0; kp < 10; ++kp)
            #pragma unroll
            for (int g = 0; g < 4; ++g)
                w2[kp][g] = pack2(Wh[(k0 + 2 * kp)     * 400 + g * 100 + j],
                                  Wh[(k0 + 2 * kp + 1) * 400 + g * 100 + j]);
    }
    if (red) h_s[j] = 0.0f;
    float c = 0.0f;
    __syncthreads();

    const float* __restrict__ zbase = g_zx + (size_t)b * TLEN * 400;
    float* __restrict__ ybase = g_seq + (size_t)b * TLEN * 100;

    float4 zb0 = make_float4(0, 0, 0, 0), zb1 = zb0;
    if (red) {
        zb0 = *reinterpret_cast<const float4*>(zbase + j * 4);
        zb1 = *reinterpret_cast<const float4*>(zbase + 400 + j * 4);
    }

    auto step = [&](int t, float4& zslot) {
        float4 zc;
        if (red) {
            zc = zslot;
            int tp = (t + 2 < TLEN) ? t + 2 : t;
            zslot = *reinterpret_cast<const float4*>(zbase + (size_t)tp * 400 + j * 4);
        }
        if (ga) {
            u64 a0 = 0ull, a1 = 0ull, a2 = 0ull, a3 = 0ull;
            const ulonglong2* hp = reinterpret_cast<const ulonglong2*>(h_s);
            const int qb = s * 5;
            #pragma unroll
            for (int q = 0; q < 5; ++q) {
                ulonglong2 hv = hp[qb + q];
                FMA2(a0, hv.x, w2[2 * q][0], a0);
                FMA2(a1, hv.x, w2[2 * q][1], a1);
                FMA2(a2, hv.x, w2[2 * q][2], a2);
                FMA2(a3, hv.x, w2[2 * q][3], a3);
                FMA2(a0, hv.y, w2[2 * q + 1][0], a0);
                FMA2(a1, hv.y, w2[2 * q + 1][1], a1);
                FMA2(a2, hv.y, w2[2 * q + 1][2], a2);
                FMA2(a3, hv.y, w2[2 * q + 1][3], a3);
            }
            float2 p0 = unpack2(a0), p1 = unpack2(a1), p2 = unpack2(a2), p3 = unpack2(a3);
            zp[s][j] = make_float4(p0.x + p0.y, p1.x + p1.y, p2.x + p2.y, p3.x + p3.y);
        }
        __syncthreads();
        if (red) {
            float z0 = zc.x, z1 = zc.y, z2 = zc.z, z3 = zc.w;
            #pragma unroll
            for (int ss = 0; ss < 5; ++ss) {
                float4 p = zp[ss][j];
                z0 += p.x; z1 += p.y; z2 += p.z; z3 += p.w;
            }
            float gi = sigm(z0), gf = sigm(z1), gg = tanh_fast(z2), go = sigm(z3);
            c = gf * c + gi * gg;
            float h = go * tanh_fast(c);
            h_s[j] = h;
            ybase[(size_t)t * 100 + j] = h;
        }
        __syncthreads();
    };

    for (int t = 0; t < TLEN; t += 2) {
        step(t,     zb0);
        step(t + 1, zb1);
    }
}

// ---------------------------------------------------------------------------
// H=200 scan (R7, proven): cluster of 4 CTAs; rank owns j-slice [50r,50r+50);
// cluster owns 4 batch rows. Wh slice in regs (k-paired f32x2); h double-
// buffered in SMEM; per-step sync = st.async tx-counted DSMEM broadcast +
// mbarrier parity wait.
// ---------------------------------------------------------------------------
template <int WRITE_Y>
__global__ void __launch_bounds__(512, 1) __cluster_dims__(4, 1, 1)
scan200(const float* __restrict__ Wh)
{
    __shared__ __align__(16) float  h_s[2][4][208];   // [buf][row][k]
    __shared__ __align__(16) float4 zp[10][4][50];    // [split][row][jl]
    __shared__ __align__(8)  u64    hbar;             // tx-counted mbarrier

    const int tid = threadIdx.x;
    uint32_t rank;
    asm("mov.u32 %0, %%cluster_ctarank;" : "=r"(rank));
    const int cl = blockIdx.x >> 2;

    const int s  = tid / 50;               // gemm split 0..9 (tid<500)
    const int jl = tid % 50;
    const bool ga  = (tid < 500);
    const bool red = (tid < 200);          // reduce row = s (0..3)
    const int  rr  = s;
    const int  jg  = (int)rank * 50 + jl;

    uint32_t hs_addr, bar_addr;
    {
        const void* p = (const void*)&h_s[0][0][0];
        asm("{ .reg .u64 t; cvta.to.shared.u64 t, %1; cvt.u32.u64 %0, t; }"
            : "=r"(hs_addr) : "l"(p));
        const void* q = (const void*)&hbar;
        asm("{ .reg .u64 t; cvta.to.shared.u64 t, %1; cvt.u32.u64 %0, t; }"
            : "=r"(bar_addr) : "l"(q));
    }

    u64 w2[10][4];   // [k-pair][gate] = {W[k][g][jg], W[k+1][g][jg]}
    if (ga) {
        const int k0 = s * 20;
        #pragma unroll
        for (int kp = 0; kp < 10; ++kp)
            #pragma unroll
            for (int g = 0; g < 4; ++g)
                w2[kp][g] = pack2(Wh[(k0 + 2 * kp)     * 800 + g * 200 + jg],
                                  Wh[(k0 + 2 * kp + 1) * 800 + g * 200 + jg]);
    }
    for (int i = tid; i < 2 * 4 * 208; i += 512) (&h_s[0][0][0])[i] = 0.0f;
    if (tid == 0) {
        asm volatile("mbarrier.init.shared.b64 [%0], %1;"
                     :: "r"(bar_addr), "r"(1u) : "memory");
    }
    float c = 0.0f;
    __syncthreads();
    asm volatile("barrier.cluster.arrive.aligned;" ::: "memory");
    asm volatile("barrier.cluster.wait.aligned;" ::: "memory");

    const int b = cl * 4 + rr;
    const float* __restrict__ zbase = g_zx + (size_t)b * TLEN * 800;
    float* __restrict__ ybase = g_seq + (size_t)b * TLEN * 200;

    float4 zb0 = make_float4(0, 0, 0, 0), zb1 = zb0;
    if (red) {
        zb0 = *reinterpret_cast<const float4*>(zbase + jg * 4);
        zb1 = *reinterpret_cast<const float4*>(zbase + 800 + jg * 4);
    }

    constexpr uint32_t TX_BYTES = 4u * 200u * 4u;   // 4 source CTAs x 200 floats

    auto step = [&](int t, float4& zslot, int cur) {
        if (tid == 0) {
            asm volatile("mbarrier.arrive.expect_tx.shared.b64 _, [%0], %1;"
                         :: "r"(bar_addr), "r"(TX_BYTES) : "memory");
        }
        float4 zc;
        if (red) {
            zc = zslot;
            int tp = (t + 2 < TLEN) ? t + 2 : t;
            zslot = *reinterpret_cast<const float4*>(zbase + (size_t)tp * 800 + jg * 4);
        }
        if (ga) {
            const int qb = s * 5;
            #pragma unroll
            for (int r2 = 0; r2 < 4; ++r2) {
                u64 a0 = 0ull, a1 = 0ull, a2 = 0ull, a3 = 0ull;
                const ulonglong2* hp =
                    reinterpret_cast<const ulonglong2*>(&h_s[cur][r2][0]);
                #pragma unroll
                for (int q = 0; q < 5; ++q) {
                    ulonglong2 hv = hp[qb + q];
                    FMA2(a0, hv.x, w2[2 * q][0], a0);
                    FMA2(a1, hv.x, w2[2 * q][1], a1);
                    FMA2(a2, hv.x, w2[2 * q][2], a2);
                    FMA2(a3, hv.x, w2[2 * q][3], a3);
                    FMA2(a0, hv.y, w2[2 * q + 1][0], a0);
                    FMA2(a1, hv.y, w2[2 * q + 1][1], a1);
                    FMA2(a2, hv.y, w2[2 * q + 1][2], a2);
                    FMA2(a3, hv.y, w2[2 * q + 1][3], a3);
                }
                float2 p0 = unpack2(a0), p1 = unpack2(a1),
                       p2 = unpack2(a2), p3 = unpack2(a3);
                zp[s][r2][jl] = make_float4(p0.x + p0.y, p1.x + p1.y,
                                            p2.x + p2.y, p3.x + p3.y);
            }
        }
        __syncthreads();
        if (red) {
            float z0 = zc.x, z1 = zc.y, z2 = zc.z, z3 = zc.w;
            #pragma unroll
            for (int ss = 0; ss < 10; ++ss) {
                float4 p = zp[ss][rr][jl];
                z0 += p.x; z1 += p.y; z2 += p.z; z3 += p.w;
            }
            float gi = sigm(z0), gf = sigm(z1), gg = tanh_fast(z2), go = sigm(z3);
            c = gf * c + gi * gg;
            float h = go * tanh_fast(c);

            const int nxt = cur ^ 1;
            uint32_t laddr = hs_addr + (uint32_t)((nxt * 4 + rr) * 208 + jg) * 4u;
            #pragma unroll
            for (int p = 0; p < 4; ++p) {
                uint32_t rdata, rbar;
                asm("mapa.shared::cluster.u32 %0, %1, %2;"
                    : "=r"(rdata) : "r"(laddr), "r"(p));
                asm("mapa.shared::cluster.u32 %0, %1, %2;"
                    : "=r"(rbar) : "r"(bar_addr), "r"(p));
                asm volatile(
                    "st.async.shared::cluster.mbarrier::complete_tx::bytes.f32 "
                    "[%0], %1, [%2];"
                    :: "r"(rdata), "f"(h), "r"(rbar) : "memory");
            }
            if (WRITE_Y) ybase[(size_t)t * 200 + jg] = h;
            if (t == TLEN - 1) g_hbuf[b * HPAD + jg] = h;
        }
        mbar_wait_parity_cluster(bar_addr, (uint32_t)(t & 1));
    };

    for (int t = 0; t < TLEN; t += 2) {
        step(t,     zb0, 0);
        step(t + 1, zb1, 1);
    }

    asm volatile("barrier.cluster.arrive.aligned;" ::: "memory");
    asm volatile("barrier.cluster.wait.aligned;" ::: "memory");
}

// Final dense: out[b, o] = h_last[b, :200] @ Wd + bd.
__global__ void dense_kernel(const float* __restrict__ Wd,
                             const float* __restrict__ bd,
                             float* __restrict__ out)
{
    int idx = blockIdx.x * blockDim.x + threadIdx.x;
    if (idx >= BSZ * 6) return;
    int b = idx / 6, o = idx - b * 6;
    const float* h = g_hbuf + b * HPAD;
    float s = bd[o];
    #pragma unroll 8
    for (int k = 0; k < 200; ++k) s += h[k] * Wd[k * 6 + o];
    out[idx] = s;
}

extern "C" void kernel_launch(void* const* d_in, const int* in_sizes, int n_in,
                              void* d_out, int out_size)
{
    const float* xs  = (const float*)d_in[0];
    const float* Wx0 = (const float*)d_in[1];
    const float* Wh0 = (const float*)d_in[2];
    const float* b0  = (const float*)d_in[3];
    const float* Wx1 = (const float*)d_in[4];
    const float* Wh1 = (const float*)d_in[5];
    const float* b1  = (const float*)d_in[6];
    const float* Wx2 = (const float*)d_in[7];
    const float* Wh2 = (const float*)d_in[8];
    const float* b2  = (const float*)d_in[9];
    const float* Wx3 = (const float*)d_in[10];
    const float* Wh3 = (const float*)d_in[11];
    const float* b3  = (const float*)d_in[12];
    const float* Wd  = (const float*)d_in[13];
    const float* bd  = (const float*)d_in[14];

    const dim3 gN400(4, 1024);   // ceil(400/128) x (131072/128)
    const dim3 gN800(7, 1024);   // ceil(800/128)

    // K2P per K: K=128 -> 64, K=100 -> 56, K=200 -> 104
    auto nA = [](int k2p) { return (unsigned)(((size_t)MTOT * k2p + 255) / 256); };
    auto nW = [](int k2p, int nwp) { return (unsigned)((k2p * nwp + 255) / 256); };

    // L0: K=128, N=400, NWP=512, Hn=100
    split_w<<<nW(64, 512), 256>>>(Wx0, 128, 400, 100, 512, 64);
    split_a<<<nA(64), 256>>>(xs, 128, 64, 0);
    gemm_bf16p<128><<<gN400, 256>>>(b0, 400, 512, 100);
    scan100<<<BSZ, 512>>>(Wh0);
    // L1: K=100, N=400, NWP=512
    split_w<<<nW(56, 512), 256>>>(Wx1, 100, 400, 100, 512, 56);
    split_a<<<nA(56), 256>>>(nullptr, 100, 56, 1);
    gemm_bf16p<100><<<gN400, 256>>>(b1, 400, 512, 100);
    scan100<<<BSZ, 512>>>(Wh1);
    // L2: K=100, N=800, NWP=896
    split_w<<<nW(56, 896), 256>>>(Wx2, 100, 800, 200, 896, 56);
    split_a<<<nA(56), 256>>>(nullptr, 100, 56, 1);
    gemm_bf16p<100><<<gN800, 256>>>(b2, 800, 896, 200);
    scan200<1><<<BSZ, 512>>>(Wh2);
    // L3: K=200, N=800, NWP=896
    split_w<<<nW(104, 896), 256>>>(Wx3, 200, 800, 200, 896, 104);
    split_a<<<nA(104), 256>>>(nullptr, 200, 104, 1);
    gemm_bf16p<200><<<gN800, 256>>>(b3, 800, 896, 200);
    scan200<0><<<BSZ, 512>>>(Wh3);
    // head
    dense_kernel<<<3, 256>>>(Wd, bd, (float*)d_out);
}

// round 16
// speedup vs baseline: 1.0117x; 1.0117x over previous
#include <cuda_runtime.h>
#include <cstdint>

// ---------------------------------------------------------------------------
// 4-layer LSTM (B=128, T=1024, D=128, H=[100,100,200,200]) + dense head.
// R15: GEMM MMA schedule reordered to break accumulator RAW chains — n-tiles
// processed in pairs, term-major (hh/lh/hl) inside the pair, so dependent
// MMAs are 4 apart instead of adjacent. Everything else identical to R14
// (pre-split bf16 planes; scans = R7 baseline).
// ---------------------------------------------------------------------------

#define TLEN 1024
#define BSZ  128
#define HPAD 256
#define MTOT (BSZ * TLEN)

typedef unsigned long long u64;
typedef unsigned int u32;

__device__ float g_zx[(size_t)BSZ * TLEN * 800];  // x@Wx+b, layout [b][t][j][4]
__device__ float g_seq[(size_t)BSZ * TLEN * 200]; // layer output sequence
__device__ float g_hbuf[BSZ * HPAD];              // final h for dense head

// pre-split planes (max K2P = 104 for K=200; max NWP = 896 for N=800)
__device__ u32 g_Ah[(size_t)MTOT * 104];
__device__ u32 g_Al[(size_t)MTOT * 104];
__device__ u32 g_Wh[104 * 896];
__device__ u32 g_Wl[104 * 896];

#define FMA2(d, a, b, c) \
    asm("fma.rn.f32x2 %0, %1, %2, %3;" : "=l"(d) : "l"(a), "l"(b), "l"(c))

__device__ __forceinline__ u64 pack2(float lo, float hi) {
    u64 d;
    asm("mov.b64 %0, {%1, %2};" : "=l"(d)
        : "r"(__float_as_uint(lo)), "r"(__float_as_uint(hi)));
    return d;
}
__device__ __forceinline__ float2 unpack2(u64 v) {
    unsigned lo, hi;
    asm("mov.b64 {%0, %1}, %2;" : "=r"(lo), "=r"(hi) : "l"(v));
    return make_float2(__uint_as_float(lo), __uint_as_float(hi));
}

__device__ __forceinline__ float sigm(float x) {
    return __fdividef(1.0f, 1.0f + __expf(-x));
}
__device__ __forceinline__ float tanh_fast(float x) {
    return 1.0f - __fdividef(2.0f, __expf(2.0f * x) + 1.0f);
}

__device__ __forceinline__ void mbar_wait_parity_cluster(uint32_t bar, uint32_t parity) {
    uint32_t done;
    asm volatile(
        "{\n\t.reg .pred p;\n\t"
        "mbarrier.try_wait.parity.acquire.cluster.shared::cta.b64 p, [%1], %2;\n\t"
        "selp.b32 %0, 1, 0, p;\n\t}"
        : "=r"(done) : "r"(bar), "r"(parity) : "memory");
    if (!done) {
        asm volatile(
            "{\n\t.reg .pred P1;\n\t"
            "WAIT_LOOP_%=:\n\t"
            "mbarrier.try_wait.parity.acquire.cluster.shared::cta.b64 P1, [%0], %1, 0x989680;\n\t"
            "@P1 bra.uni WAIT_DONE_%=;\n\t"
            "bra.uni WAIT_LOOP_%=;\n\t"
            "WAIT_DONE_%=:\n\t}"
            :: "r"(bar), "r"(parity) : "memory");
    }
}

// ---------------------------------------------------------------------------
// bf16 helpers
// ---------------------------------------------------------------------------
__device__ __forceinline__ u32 bf16x2_of(float f0, float f1) {
    u32 r;   // f0 -> low half, f1 -> high half
    asm("cvt.rn.bf16x2.f32 %0, %1, %2;" : "=r"(r) : "f"(f1), "f"(f0));
    return r;
}
__device__ __forceinline__ float bf_lo_f(u32 v) { return __uint_as_float(v << 16); }
__device__ __forceinline__ float bf_hi_f(u32 v) { return __uint_as_float(v & 0xffff0000u); }

__device__ __forceinline__ void mma_bf16(float* c, const u32* a, const u32* b) {
    asm volatile(
        "mma.sync.aligned.m16n8k16.row.col.f32.bf16.bf16.f32 "
        "{%0,%1,%2,%3}, {%4,%5,%6,%7}, {%8,%9}, {%0,%1,%2,%3};"
        : "+f"(c[0]), "+f"(c[1]), "+f"(c[2]), "+f"(c[3])
        : "r"(a[0]), "r"(a[1]), "r"(a[2]), "r"(a[3]), "r"(b[0]), "r"(b[1]));
}

// slot -> k2 offset within an 8-slot chunk (inverse of p(k2)=(k2&3)*2+(k2>>2))
__device__ __forceinline__ int invp(int p) {
    return (p & 1) ? (4 + (p >> 1)) : (p >> 1);
}

// ---------------------------------------------------------------------------
// Pre-split A: float [M][K] -> u32 hi/lo planes [M][K2P] (bf16x2 k-pairs,
// permuted within each 8-slot chunk; zero-padded beyond K).
// ---------------------------------------------------------------------------
__global__ void split_a(const float* __restrict__ Ain, int K, int K2P, int use_seq)
{
    const float* __restrict__ A = use_seq ? g_seq : Ain;
    size_t idx = (size_t)blockIdx.x * blockDim.x + threadIdx.x;
    size_t total = (size_t)MTOT * K2P;
    if (idx >= total) return;
    int s   = (int)(idx % K2P);
    size_t row = idx / K2P;
    int k2  = (s & ~7) + invp(s & 7);
    int k   = 2 * k2;
    float x0 = (k     < K) ? A[row * K + k]     : 0.0f;
    float x1 = (k + 1 < K) ? A[row * K + k + 1] : 0.0f;
    u32 hi = bf16x2_of(x0, x1);
    u32 lo = bf16x2_of(x0 - bf_lo_f(hi), x1 - bf_hi_f(hi));
    g_Ah[idx] = hi;
    g_Al[idx] = lo;
}

// ---------------------------------------------------------------------------
// Pre-split W: float [K][Nw] -> u32 hi/lo planes [K2P][NWP] with the output
// column map baked in (col n <- W col (n&3)*Hn + (n>>2)); zero-padded.
// ---------------------------------------------------------------------------
__global__ void split_w(const float* __restrict__ W,
                        int K, int N, int Hn, int NWP, int K2P)
{
    int idx = blockIdx.x * blockDim.x + threadIdx.x;
    int total = K2P * NWP;
    if (idx >= total) return;
    int s = idx / NWP;
    int n = idx % NWP;
    int k2 = (s & ~7) + invp(s & 7);
    int k  = 2 * k2;
    int wsrc = (n & 3) * Hn + (n >> 2);
    float x0 = (k     < K && n < N) ? W[(size_t)k * N + wsrc]       : 0.0f;
    float x1 = (k + 1 < K && n < N) ? W[(size_t)(k + 1) * N + wsrc] : 0.0f;
    u32 hi = bf16x2_of(x0, x1);
    u32 lo = bf16x2_of(x0 - bf_lo_f(hi), x1 - bf_hi_f(hi));
    g_Wh[idx] = hi;
    g_Wl[idx] = lo;
}

// ---------------------------------------------------------------------------
// Lean bf16 tensor-core GEMM (3-term split hh+lh+hl) on pre-split planes.
// R15: n-tiles in pairs, term-major MMA order -> dependent MMAs 4 apart.
// 128x128 CTA tile, 256 threads, 8 warps (32x64), KC=16 double-buffered.
// ---------------------------------------------------------------------------
template <int K>
__global__ void __launch_bounds__(256, 2)
gemm_bf16p(const float* __restrict__ bias, int N, int NWP, int Hn)
{
    constexpr int KC  = 16;
    constexpr int NCH = (K + KC - 1) / KC;
    constexpr int K2P = NCH * 8;
    constexpr int LDQ = 10;                   // u32 row stride (8 + pad, 8B-aligned)

    __shared__ __align__(16) u32 Ah[2][128][LDQ], Al[2][128][LDQ];
    __shared__ __align__(16) u32 Bh[2][128][LDQ], Bl[2][128][LDQ];

    const int tid  = threadIdx.x;
    const int m0   = blockIdx.y * 128, n0 = blockIdx.x * 128;
    const int warp = tid >> 5, lane = tid & 31;
    const int g    = lane >> 2, tig = lane & 3;
    const int wm   = (warp >> 1) * 32, wn = (warp & 1) * 64;

    // staging roles: d = row/col (tid>>1), half = k-half (tid&1: 4 slots each)
    const int sd = tid >> 1, sh = tid & 1;

    u32 aRh[4], aRl[4], bRh[4], bRl[4];

    auto ldA = [&](int c) {
        size_t off = (size_t)(m0 + sd) * K2P + c * 8 + sh * 4;
        uint2 h0 = *reinterpret_cast<const uint2*>(&g_Ah[off]);
        uint2 h1 = *reinterpret_cast<const uint2*>(&g_Ah[off + 2]);
        uint2 l0 = *reinterpret_cast<const uint2*>(&g_Al[off]);
        uint2 l1 = *reinterpret_cast<const uint2*>(&g_Al[off + 2]);
        aRh[0] = h0.x; aRh[1] = h0.y; aRh[2] = h1.x; aRh[3] = h1.y;
        aRl[0] = l0.x; aRl[1] = l0.y; aRl[2] = l1.x; aRl[3] = l1.y;
    };
    auto ldB = [&](int c) {
        #pragma unroll
        for (int e = 0; e < 4; ++e) {
            int s = c * 8 + sh * 4 + e;
            bRh[e] = g_Wh[(size_t)s * NWP + n0 + sd];
            bRl[e] = g_Wl[(size_t)s * NWP + n0 + sd];
        }
    };
    auto stA = [&](int buf) {
        #pragma unroll
        for (int e = 0; e < 4; ++e) {
            Ah[buf][sd][sh * 4 + e] = aRh[e];
            Al[buf][sd][sh * 4 + e] = aRl[e];
        }
    };
    auto stB = [&](int buf) {
        #pragma unroll
        for (int e = 0; e < 4; ++e) {
            Bh[buf][sd][sh * 4 + e] = bRh[e];
            Bl[buf][sd][sh * 4 + e] = bRl[e];
        }
    };

    ldA(0); ldB(0);
    stA(0); stB(0);
    __syncthreads();

    float acc[2][8][4];
    #pragma unroll
    for (int mt = 0; mt < 2; ++mt)
        #pragma unroll
        for (int nt = 0; nt < 8; ++nt)
            #pragma unroll
            for (int i = 0; i < 4; ++i) acc[mt][nt][i] = 0.0f;

    for (int c = 0; c < NCH; ++c) {
        const int buf = c & 1;
        if (c + 1 < NCH) { ldA(c + 1); ldB(c + 1); }

        u32 ah[2][4], al[2][4];
        #pragma unroll
        for (int mt = 0; mt < 2; ++mt) {
            int row = wm + mt * 16 + g;
            uint2 t;
            t = *reinterpret_cast<const uint2*>(&Ah[buf][row][2 * tig]);
            ah[mt][0] = t.x; ah[mt][2] = t.y;
            t = *reinterpret_cast<const uint2*>(&Ah[buf][row + 8][2 * tig]);
            ah[mt][1] = t.x; ah[mt][3] = t.y;
            t = *reinterpret_cast<const uint2*>(&Al[buf][row][2 * tig]);
            al[mt][0] = t.x; al[mt][2] = t.y;
            t = *reinterpret_cast<const uint2*>(&Al[buf][row + 8][2 * tig]);
            al[mt][1] = t.x; al[mt][3] = t.y;
        }
        // n-tiles in pairs; term-major inside the pair so consecutive MMAs
        // hit distinct accumulators (dependent-reuse distance = 4 MMAs).
        #pragma unroll
        for (int np = 0; np < 4; ++np) {
            u32 bh2[2][2], bl2[2][2];
            #pragma unroll
            for (int q = 0; q < 2; ++q) {
                int coln = wn + (np * 2 + q) * 8 + g;
                uint2 t;
                t = *reinterpret_cast<const uint2*>(&Bh[buf][coln][2 * tig]);
                bh2[q][0] = t.x; bh2[q][1] = t.y;
                t = *reinterpret_cast<const uint2*>(&Bl[buf][coln][2 * tig]);
                bl2[q][0] = t.x; bl2[q][1] = t.y;
            }
            // term hh
            #pragma unroll
            for (int q = 0; q < 2; ++q)
                #pragma unroll
                for (int mt = 0; mt < 2; ++mt)
                    mma_bf16(acc[mt][np * 2 + q], ah[mt], bh2[q]);
            // term lh
            #pragma unroll
            for (int q = 0; q < 2; ++q)
                #pragma unroll
                for (int mt = 0; mt < 2; ++mt)
                    mma_bf16(acc[mt][np * 2 + q], al[mt], bh2[q]);
            // term hl
            #pragma unroll
            for (int q = 0; q < 2; ++q)
                #pragma unroll
                for (int mt = 0; mt < 2; ++mt)
                    mma_bf16(acc[mt][np * 2 + q], ah[mt], bl2[q]);
        }
        if (c + 1 < NCH) { stA(buf ^ 1); stB(buf ^ 1); }
        __syncthreads();
    }

    // epilogue: bias (permuted) + store
    #pragma unroll
    for (int nt = 0; nt < 8; ++nt) {
        int col = n0 + wn + nt * 8 + tig * 2;
        if (col >= N) continue;
        float b0 = bias[(col & 3) * Hn + (col >> 2)];
        float b1 = bias[((col + 1) & 3) * Hn + ((col + 1) >> 2)];
        #pragma unroll
        for (int mt = 0; mt < 2; ++mt) {
            int row = m0 + wm + mt * 16 + g;
            float2 v0 = make_float2(acc[mt][nt][0] + b0, acc[mt][nt][1] + b1);
            float2 v1 = make_float2(acc[mt][nt][2] + b0, acc[mt][nt][3] + b1);
            *reinterpret_cast<float2*>(&g_zx[(size_t)row * N + col])       = v0;
            *reinterpret_cast<float2*>(&g_zx[(size_t)(row + 8) * N + col]) = v1;
        }
    }
}

// ---------------------------------------------------------------------------
// H=100 scan (R7, proven): 1 CTA per batch row, Wh in regs (k-paired f32x2),
// h in SMEM, zx float4 with 2-deep register prefetch ring.
// ---------------------------------------------------------------------------
__global__ void __launch_bounds__(512, 1)
scan100(const float* __restrict__ Wh)
{
    __shared__ __align__(16) float  h_s[104];
    __shared__ __align__(16) float4 zp[5][100];

    const int tid = threadIdx.x;
    const int b   = blockIdx.x;
    const int s   = tid / 100;
    const int j   = tid % 100;
    const bool ga  = (tid < 500);
    const bool red = (tid < 100);

    u64 w2[10][4];
    if (ga) {
        const int k0 = s * 20;
        #pragma unroll
        for (int kp = 0; kp < 10; ++kp)
            #pragma unroll
            for (int g = 0; g < 4; ++g)
                w2[kp][g] = pack2(Wh[(k0 + 2 * kp)     * 400 + g * 100 + j],
                                  Wh[(k0 + 2 * kp + 1) * 400 + g * 100 + j]);
    }
    if (red) h_s[j] = 0.0f;
    float c = 0.0f;
    __syncthreads();

    const float* __restrict__ zbase = g_zx + (size_t)b * TLEN * 400;
    float* __restrict__ ybase = g_seq + (size_t)b * TLEN * 100;

    float4 zb0 = make_float4(0, 0, 0, 0), zb1 = zb0;
    if (red) {
        zb0 = *reinterpret_cast<const float4*>(zbase + j * 4);
        zb1 = *reinterpret_cast<const float4*>(zbase + 400 + j * 4);
    }

    auto step = [&](int t, float4& zslot) {
        float4 zc;
        if (red) {
            zc = zslot;
            int tp = (t + 2 < TLEN) ? t + 2 : t;
            zslot = *reinterpret_cast<const float4*>(zbase + (size_t)tp * 400 + j * 4);
        }
        if (ga) {
            u64 a0 = 0ull, a1 = 0ull, a2 = 0ull, a3 = 0ull;
            const ulonglong2* hp = reinterpret_cast<const ulonglong2*>(h_s);
            const int qb = s * 5;
            #pragma unroll
            for (int q = 0; q < 5; ++q) {
                ulonglong2 hv = hp[qb + q];
                FMA2(a0, hv.x, w2[2 * q][0], a0);
                FMA2(a1, hv.x, w2[2 * q][1], a1);
                FMA2(a2, hv.x, w2[2 * q][2], a2);
                FMA2(a3, hv.x, w2[2 * q][3], a3);
                FMA2(a0, hv.y, w2[2 * q + 1][0], a0);
                FMA2(a1, hv.y, w2[2 * q + 1][1], a1);
                FMA2(a2, hv.y, w2[2 * q + 1][2], a2);
                FMA2(a3, hv.y, w2[2 * q + 1][3], a3);
            }
            float2 p0 = unpack2(a0), p1 = unpack2(a1), p2 = unpack2(a2), p3 = unpack2(a3);
            zp[s][j] = make_float4(p0.x + p0.y, p1.x + p1.y, p2.x + p2.y, p3.x + p3.y);
        }
        __syncthreads();
        if (red) {
            float z0 = zc.x, z1 = zc.y, z2 = zc.z, z3 = zc.w;
            #pragma unroll
            for (int ss = 0; ss < 5; ++ss) {
                float4 p = zp[ss][j];
                z0 += p.x; z1 += p.y; z2 += p.z; z3 += p.w;
            }
            float gi = sigm(z0), gf = sigm(z1), gg = tanh_fast(z2), go = sigm(z3);
            c = gf * c + gi * gg;
            float h = go * tanh_fast(c);
            h_s[j] = h;
            ybase[(size_t)t * 100 + j] = h;
        }
        __syncthreads();
    };

    for (int t = 0; t < TLEN; t += 2) {
        step(t,     zb0);
        step(t + 1, zb1);
    }
}

// ---------------------------------------------------------------------------
// H=200 scan (R7, proven): cluster of 4 CTAs; rank owns j-slice [50r,50r+50);
// cluster owns 4 batch rows. Wh slice in regs (k-paired f32x2); h double-
// buffered in SMEM; per-step sync = st.async tx-counted DSMEM broadcast +
// mbarrier parity wait.
// ---------------------------------------------------------------------------
template <int WRITE_Y>
__global__ void __launch_bounds__(512, 1) __cluster_dims__(4, 1, 1)
scan200(const float* __restrict__ Wh)
{
    __shared__ __align__(16) float  h_s[2][4][208];   // [buf][row][k]
    __shared__ __align__(16) float4 zp[10][4][50];    // [split][row][jl]
    __shared__ __align__(8)  u64    hbar;             // tx-counted mbarrier

    const int tid = threadIdx.x;
    uint32_t rank;
    asm("mov.u32 %0, %%cluster_ctarank;" : "=r"(rank));
    const int cl = blockIdx.x >> 2;

    const int s  = tid / 50;               // gemm split 0..9 (tid<500)
    const int jl = tid % 50;
    const bool ga  = (tid < 500);
    const bool red = (tid < 200);          // reduce row = s (0..3)
    const int  rr  = s;
    const int  jg  = (int)rank * 50 + jl;

    uint32_t hs_addr, bar_addr;
    {
        const void* p = (const void*)&h_s[0][0][0];
        asm("{ .reg .u64 t; cvta.to.shared.u64 t, %1; cvt.u32.u64 %0, t; }"
            : "=r"(hs_addr) : "l"(p));
        const void* q = (const void*)&hbar;
        asm("{ .reg .u64 t; cvta.to.shared.u64 t, %1; cvt.u32.u64 %0, t; }"
            : "=r"(bar_addr) : "l"(q));
    }

    u64 w2[10][4];   // [k-pair][gate] = {W[k][g][jg], W[k+1][g][jg]}
    if (ga) {
        const int k0 = s * 20;
        #pragma unroll
        for (int kp = 0; kp < 10; ++kp)
            #pragma unroll
            for (int g = 0; g < 4; ++g)
                w2[kp][g] = pack2(Wh[(k0 + 2 * kp)     * 800 + g * 200 + jg],
                                  Wh[(k0 + 2 * kp + 1) * 800 + g * 200 + jg]);
    }
    for (int i = tid; i < 2 * 4 * 208; i += 512) (&h_s[0][0][0])[i] = 0.0f;
    if (tid == 0) {
        asm volatile("mbarrier.init.shared.b64 [%0], %1;"
                     :: "r"(bar_addr), "r"(1u) : "memory");
    }
    float c = 0.0f;
    __syncthreads();
    asm volatile("barrier.cluster.arrive.aligned;" ::: "memory");
    asm volatile("barrier.cluster.wait.aligned;" ::: "memory");

    const int b = cl * 4 + rr;
    const float* __restrict__ zbase = g_zx + (size_t)b * TLEN * 800;
    float* __restrict__ ybase = g_seq + (size_t)b * TLEN * 200;

    float4 zb0 = make_float4(0, 0, 0, 0), zb1 = zb0;
    if (red) {
        zb0 = *reinterpret_cast<const float4*>(zbase + jg * 4);
        zb1 = *reinterpret_cast<const float4*>(zbase + 800 + jg * 4);
    }

    constexpr uint32_t TX_BYTES = 4u * 200u * 4u;   // 4 source CTAs x 200 floats

    auto step = [&](int t, float4& zslot, int cur) {
        if (tid == 0) {
            asm volatile("mbarrier.arrive.expect_tx.shared.b64 _, [%0], %1;"
                         :: "r"(bar_addr), "r"(TX_BYTES) : "memory");
        }
        float4 zc;
        if (red) {
            zc = zslot;
            int tp = (t + 2 < TLEN) ? t + 2 : t;
            zslot = *reinterpret_cast<const float4*>(zbase + (size_t)tp * 800 + jg * 4);
        }
        if (ga) {
            const int qb = s * 5;
            #pragma unroll
            for (int r2 = 0; r2 < 4; ++r2) {
                u64 a0 = 0ull, a1 = 0ull, a2 = 0ull, a3 = 0ull;
                const ulonglong2* hp =
                    reinterpret_cast<const ulonglong2*>(&h_s[cur][r2][0]);
                #pragma unroll
                for (int q = 0; q < 5; ++q) {
                    ulonglong2 hv = hp[qb + q];
                    FMA2(a0, hv.x, w2[2 * q][0], a0);
                    FMA2(a1, hv.x, w2[2 * q][1], a1);
                    FMA2(a2, hv.x, w2[2 * q][2], a2);
                    FMA2(a3, hv.x, w2[2 * q][3], a3);
                    FMA2(a0, hv.y, w2[2 * q + 1][0], a0);
                    FMA2(a1, hv.y, w2[2 * q + 1][1], a1);
                    FMA2(a2, hv.y, w2[2 * q + 1][2], a2);
                    FMA2(a3, hv.y, w2[2 * q + 1][3], a3);
                }
                float2 p0 = unpack2(a0), p1 = unpack2(a1),
                       p2 = unpack2(a2), p3 = unpack2(a3);
                zp[s][r2][jl] = make_float4(p0.x + p0.y, p1.x + p1.y,
                                            p2.x + p2.y, p3.x + p3.y);
            }
        }
        __syncthreads();
        if (red) {
            float z0 = zc.x, z1 = zc.y, z2 = zc.z, z3 = zc.w;
            #pragma unroll
            for (int ss = 0; ss < 10; ++ss) {
                float4 p = zp[ss][rr][jl];
                z0 += p.x; z1 += p.y; z2 += p.z; z3 += p.w;
            }
            float gi = sigm(z0), gf = sigm(z1), gg = tanh_fast(z2), go = sigm(z3);
            c = gf * c + gi * gg;
            float h = go * tanh_fast(c);

            const int nxt = cur ^ 1;
            uint32_t laddr = hs_addr + (uint32_t)((nxt * 4 + rr) * 208 + jg) * 4u;
            #pragma unroll
            for (int p = 0; p < 4; ++p) {
                uint32_t rdata, rbar;
                asm("mapa.shared::cluster.u32 %0, %1, %2;"
                    : "=r"(rdata) : "r"(laddr), "r"(p));
                asm("mapa.shared::cluster.u32 %0, %1, %2;"
                    : "=r"(rbar) : "r"(bar_addr), "r"(p));
                asm volatile(
                    "st.async.shared::cluster.mbarrier::complete_tx::bytes.f32 "
                    "[%0], %1, [%2];"
                    :: "r"(rdata), "f"(h), "r"(rbar) : "memory");
            }
            if (WRITE_Y) ybase[(size_t)t * 200 + jg] = h;
            if (t == TLEN - 1) g_hbuf[b * HPAD + jg] = h;
        }
        mbar_wait_parity_cluster(bar_addr, (uint32_t)(t & 1));
    };

    for (int t = 0; t < TLEN; t += 2) {
        step(t,     zb0, 0);
        step(t + 1, zb1, 1);
    }

    asm volatile("barrier.cluster.arrive.aligned;" ::: "memory");
    asm volatile("barrier.cluster.wait.aligned;" ::: "memory");
}

// Final dense: out[b, o] = h_last[b, :200] @ Wd + bd.
__global__ void dense_kernel(const float* __restrict__ Wd,
                             const float* __restrict__ bd,
                             float* __restrict__ out)
{
    int idx = blockIdx.x * blockDim.x + threadIdx.x;
    if (idx >= BSZ * 6) return;
    int b = idx / 6, o = idx - b * 6;
    const float* h = g_hbuf + b * HPAD;
    float s = bd[o];
    #pragma unroll 8
    for (int k = 0; k < 200; ++k) s += h[k] * Wd[k * 6 + o];
    out[idx] = s;
}

extern "C" void kernel_launch(void* const* d_in, const int* in_sizes, int n_in,
                              void* d_out, int out_size)
{
    const float* xs  = (const float*)d_in[0];
    const float* Wx0 = (const float*)d_in[1];
    const float* Wh0 = (const float*)d_in[2];
    const float* b0  = (const float*)d_in[3];
    const float* Wx1 = (const float*)d_in[4];
    const float* Wh1 = (const float*)d_in[5];
    const float* b1  = (const float*)d_in[6];
    const float* Wx2 = (const float*)d_in[7];
    const float* Wh2 = (const float*)d_in[8];
    const float* b2  = (const float*)d_in[9];
    const float* Wx3 = (const float*)d_in[10];
    const float* Wh3 = (const float*)d_in[11];
    const float* b3  = (const float*)d_in[12];
    const float* Wd  = (const float*)d_in[13];
    const float* bd  = (const float*)d_in[14];

    const dim3 gN400(4, 1024);   // ceil(400/128) x (131072/128)
    const dim3 gN800(7, 1024);   // ceil(800/128)

    // K2P per K: K=128 -> 64, K=100 -> 56, K=200 -> 104
    auto nA = [](int k2p) { return (unsigned)(((size_t)MTOT * k2p + 255) / 256); };
    auto nW = [](int k2p, int nwp) { return (unsigned)((k2p * nwp + 255) / 256); };

    // L0: K=128, N=400, NWP=512, Hn=100
    split_w<<<nW(64, 512), 256>>>(Wx0, 128, 400, 100, 512, 64);
    split_a<<<nA(64), 256>>>(xs, 128, 64, 0);
    gemm_bf16p<128><<<gN400, 256>>>(b0, 400, 512, 100);
    scan100<<<BSZ, 512>>>(Wh0);
    // L1: K=100, N=400, NWP=512
    split_w<<<nW(56, 512), 256>>>(Wx1, 100, 400, 100, 512, 56);
    split_a<<<nA(56), 256>>>(nullptr, 100, 56, 1);
    gemm_bf16p<100><<<gN400, 256>>>(b1, 400, 512, 100);
    scan100<<<BSZ, 512>>>(Wh1);
    // L2: K=100, N=800, NWP=896
    split_w<<<nW(56, 896), 256>>>(Wx2, 100, 800, 200, 896, 56);
    split_a<<<nA(56), 256>>>(nullptr, 100, 56, 1);
    gemm_bf16p<100><<<gN800, 256>>>(b2, 800, 896, 200);
    scan200<1><<<BSZ, 512>>>(Wh2);
    // L3: K=200, N=800, NWP=896
    split_w<<<nW(104, 896), 256>>>(Wx3, 200, 800, 200, 896, 104);
    split_a<<<nA(104), 256>>>(nullptr, 200, 104, 1);
    gemm_bf16p<200><<<gN800, 256>>>(b3, 800, 896, 200);
    scan200<0><<<BSZ, 512>>>(Wh3);
    // head
    dense_kernel<<<3, 256>>>(Wd, bd, (float*)d_out);
}